// round 5
// baseline (speedup 1.0000x reference)
#include <cuda_runtime.h>

// Swin shifted-window MSA: B=32, H=W=112, C=96, ws=7, ss=3, nh=3, hd=32
// 3-kernel pipeline, all fp32:
//   k_qkv : per-window roll-gather + QKV GEMM (49x96 @ 96x288) -> scratch [win][head][qkv][n][d]
//   k_attn: per-(window,head) attention (S=qk^T + bias + analytic shift mask, softmax, P@V)
//   k_proj: per-window proj GEMM (49x96 @ 96x96) + roll-scatter to output

#define WS_ 7
#define SS_ 3
#define NH_ 3
#define HD_ 32
#define C_  96
#define N_  49
#define HW_ 112
#define B_  32
#define BNW 8192   // 32 * 16 * 16 windows

// scratch (static device globals; no allocation in kernel_launch)
__device__ float g_qkv[(size_t)BNW * 3 * 3 * N_ * HD_]; // [win][head][which][n][d]  462 MB
__device__ float g_y[(size_t)BNW * N_ * C_];            // [win][n][c]               154 MB

__device__ __forceinline__ int rcode(int h) {
    // region slices on UNSHIFTED coords: [0,105) -> 0, [105,109) -> 1, [109,112) -> 2
    return h < (HW_ - WS_) ? 0 : (h < (HW_ - SS_) ? 1 : 2);
}

// ---------------------------------------------------------------------------
// Kernel 1: QKV projection. grid = BNW, block = 256.
// ---------------------------------------------------------------------------
__global__ __launch_bounds__(256) void k_qkv(
    const float* __restrict__ x,
    const float* __restrict__ qkv_w,
    const float* __restrict__ qkv_b)
{
    __shared__ float xs[50][100];  // padded rows (bank) + pad row 49
    __shared__ float wt[48][96];   // half of a 96x96 weight tile

    const int bw  = blockIdx.x;
    const int tid = threadIdx.x;
    const int b   = bw >> 8;
    const int w   = bw & 255;
    const int wy  = w >> 4, wx = w & 15;

    // gather rolled window: token (i,j) <- x[b, (wy*7+i+3)%112, (wx*7+j+3)%112, :]
    for (int u = tid; u < N_ * 24; u += 256) {
        int n = u / 24, f = u % 24;
        int i = n / 7, j = n % 7;
        int gy = wy * 7 + i + SS_; if (gy >= HW_) gy -= HW_;
        int gx = wx * 7 + j + SS_; if (gx >= HW_) gx -= HW_;
        float4 v = *(const float4*)&x[(((size_t)b * HW_ + gy) * HW_ + gx) * C_ + f * 4];
        *(float4*)&xs[n][f * 4] = v;
    }

    const int tx = tid % 24;   // column group (4 cols each) within 96
    const int ty = tid / 24;   // 0..10 ; ty==10 idles in compute

    for (int which = 0; which < 3; which++) {
        float acc[5][4] = {};
        for (int half = 0; half < 2; half++) {
            __syncthreads();
            for (int u = tid; u < 48 * 24; u += 256) {
                int r = u / 24, f = u % 24;
                *(float4*)&wt[r][f * 4] =
                    *(const float4*)&qkv_w[(half * 48 + r) * (3 * C_) + which * C_ + f * 4];
            }
            __syncthreads();
            if (ty < 10) {
                #pragma unroll 8
                for (int kk = 0; kk < 48; kk++) {
                    float4 wv = *(float4*)&wt[kk][tx * 4];
                    #pragma unroll
                    for (int rr = 0; rr < 5; rr++) {
                        float xv = xs[ty * 5 + rr][half * 48 + kk];
                        acc[rr][0] += xv * wv.x;
                        acc[rr][1] += xv * wv.y;
                        acc[rr][2] += xv * wv.z;
                        acc[rr][3] += xv * wv.w;
                    }
                }
            }
        }
        if (ty < 10) {
            int c = tx * 4;                 // col within 96
            int head = c >> 5, d = c & 31;
            float4 bias = *(const float4*)&qkv_b[which * C_ + c];
            float scale = (which == 0) ? 0.17677669529663687f : 1.0f; // hd^-0.5 (q only)
            size_t obase = ((size_t)(bw * 3 + head) * 3 + which) * (size_t)(N_ * HD_);
            #pragma unroll
            for (int rr = 0; rr < 5; rr++) {
                int n = ty * 5 + rr;
                if (n < N_) {
                    float4 o;
                    o.x = (acc[rr][0] + bias.x) * scale;
                    o.y = (acc[rr][1] + bias.y) * scale;
                    o.z = (acc[rr][2] + bias.z) * scale;
                    o.w = (acc[rr][3] + bias.w) * scale;
                    *(float4*)&g_qkv[obase + n * HD_ + d] = o;
                }
            }
        }
    }
}

// ---------------------------------------------------------------------------
// Kernel 2: windowed attention. grid = (BNW, 3), block = 128.
// ---------------------------------------------------------------------------
__global__ __launch_bounds__(128) void k_attn(const float* __restrict__ bias_table)
{
    __shared__ float qs[52][32];
    __shared__ float kT[32][52];
    __shared__ float vs[52][32];
    __shared__ float S[52][52];
    __shared__ int   code[52];

    const int bw   = blockIdx.x;
    const int head = blockIdx.y;
    const int tid  = threadIdx.x;
    const size_t base = (size_t)(bw * 3 + head) * 3 * (size_t)(N_ * HD_);

    for (int u = tid; u < N_ * HD_; u += 128) {
        int n = u >> 5, d = u & 31;
        qs[n][d] = g_qkv[base + u];
        kT[d][n] = g_qkv[base + N_ * HD_ + u];
        vs[n][d] = g_qkv[base + 2 * N_ * HD_ + u];
    }
    {
        int w = bw & 255;
        int wy = w >> 4, wx = w & 15;
        for (int n = tid; n < N_; n += 128) {
            int i = n / 7, j = n % 7;
            int gy = wy * 7 + i + SS_; if (gy >= HW_) gy -= HW_;
            int gx = wx * 7 + j + SS_; if (gx >= HW_) gx -= HW_;
            code[n] = rcode(gy) * 3 + rcode(gx);
        }
    }
    __syncthreads();

    // S = q @ k^T  (49x49, K=32), 4x4 register tiles
    for (int u = tid; u < 169; u += 128) {
        int n0 = (u / 13) * 4, m0 = (u % 13) * 4;
        float acc[4][4] = {};
        #pragma unroll 8
        for (int kk = 0; kk < HD_; kk++) {
            float4 kv = *(float4*)&kT[kk][m0];
            #pragma unroll
            for (int r = 0; r < 4; r++) {
                float qv = qs[n0 + r][kk];
                acc[r][0] += qv * kv.x;
                acc[r][1] += qv * kv.y;
                acc[r][2] += qv * kv.z;
                acc[r][3] += qv * kv.w;
            }
        }
        #pragma unroll
        for (int r = 0; r < 4; r++) {
            float4 o; o.x = acc[r][0]; o.y = acc[r][1]; o.z = acc[r][2]; o.w = acc[r][3];
            *(float4*)&S[n0 + r][m0] = o;
        }
    }
    __syncthreads();

    // softmax over rows, with relative-position bias + shift mask (analytic)
    const int wid = tid >> 5, lane = tid & 31;
    for (int r = wid; r < N_; r += 4) {
        int i1 = r / 7, j1 = r % 7, c1 = code[r];
        int m1 = lane, m2 = lane + 32;
        int i2 = m1 / 7, j2 = m1 % 7;
        float b1 = __ldg(&bias_table[((i1 - i2 + 6) * 13 + (j1 - j2 + 6)) * NH_ + head]);
        float v1 = S[r][m1] + b1 + (code[m1] == c1 ? 0.0f : -1e9f);
        float v2 = -1e30f;
        if (m2 < N_) {
            int i3 = m2 / 7, j3 = m2 % 7;
            float b2 = __ldg(&bias_table[((i1 - i3 + 6) * 13 + (j1 - j3 + 6)) * NH_ + head]);
            v2 = S[r][m2] + b2 + (code[m2] == c1 ? 0.0f : -1e9f);
        }
        float mx = fmaxf(v1, v2);
        #pragma unroll
        for (int o = 16; o > 0; o >>= 1) mx = fmaxf(mx, __shfl_xor_sync(0xffffffffu, mx, o));
        float e1 = __expf(v1 - mx);
        float e2 = (m2 < N_) ? __expf(v2 - mx) : 0.0f;
        float sum = e1 + e2;
        #pragma unroll
        for (int o = 16; o > 0; o >>= 1) sum += __shfl_xor_sync(0xffffffffu, sum, o);
        float inv = 1.0f / sum;
        S[r][m1] = e1 * inv;
        if (m2 < N_) S[r][m2] = e2 * inv;
    }
    __syncthreads();

    // O = P @ V  (49x32, K=49), 4x4 register tiles; write [win][n][head*32+d]
    for (int u = tid; u < 104; u += 128) {
        int n0 = (u / 8) * 4, d0 = (u % 8) * 4;
        float acc[4][4] = {};
        #pragma unroll 7
        for (int m = 0; m < N_; m++) {
            float4 vm = *(float4*)&vs[m][d0];
            #pragma unroll
            for (int r = 0; r < 4; r++) {
                float p = S[n0 + r][m];
                acc[r][0] += p * vm.x;
                acc[r][1] += p * vm.y;
                acc[r][2] += p * vm.z;
                acc[r][3] += p * vm.w;
            }
        }
        #pragma unroll
        for (int r = 0; r < 4; r++) {
            int n = n0 + r;
            if (n < N_) {
                float4 o; o.x = acc[r][0]; o.y = acc[r][1]; o.z = acc[r][2]; o.w = acc[r][3];
                *(float4*)&g_y[((size_t)bw * N_ + n) * C_ + head * HD_ + d0] = o;
            }
        }
    }
}

// ---------------------------------------------------------------------------
// Kernel 3: output projection + roll-scatter. grid = BNW, block = 256.
// ---------------------------------------------------------------------------
__global__ __launch_bounds__(256) void k_proj(
    const float* __restrict__ proj_w,
    const float* __restrict__ proj_b,
    float* __restrict__ out)
{
    __shared__ float ys[50][100];
    __shared__ float wt[48][96];

    const int bw  = blockIdx.x;
    const int tid = threadIdx.x;

    for (int u = tid; u < N_ * 24; u += 256) {
        int n = u / 24, f = u % 24;
        *(float4*)&ys[n][f * 4] =
            *(const float4*)&g_y[(size_t)bw * (N_ * C_) + n * C_ + f * 4];
    }

    const int tx = tid % 24;
    const int ty = tid / 24;

    float acc[5][4] = {};
    for (int half = 0; half < 2; half++) {
        __syncthreads();
        for (int u = tid; u < 48 * 24; u += 256) {
            int r = u / 24, f = u % 24;
            *(float4*)&wt[r][f * 4] =
                *(const float4*)&proj_w[(half * 48 + r) * C_ + f * 4];
        }
        __syncthreads();
        if (ty < 10) {
            #pragma unroll 8
            for (int kk = 0; kk < 48; kk++) {
                float4 wv = *(float4*)&wt[kk][tx * 4];
                #pragma unroll
                for (int rr = 0; rr < 5; rr++) {
                    float yv = ys[ty * 5 + rr][half * 48 + kk];
                    acc[rr][0] += yv * wv.x;
                    acc[rr][1] += yv * wv.y;
                    acc[rr][2] += yv * wv.z;
                    acc[rr][3] += yv * wv.w;
                }
            }
        }
    }

    if (ty < 10) {
        const int b  = bw >> 8;
        const int w  = bw & 255;
        const int wy = w >> 4, wx = w & 15;
        float4 bias = *(const float4*)&proj_b[tx * 4];
        #pragma unroll
        for (int rr = 0; rr < 5; rr++) {
            int n = ty * 5 + rr;
            if (n < N_) {
                int i = n / 7, j = n % 7;
                int gy = wy * 7 + i + SS_; if (gy >= HW_) gy -= HW_;
                int gx = wx * 7 + j + SS_; if (gx >= HW_) gx -= HW_;
                float4 o;
                o.x = acc[rr][0] + bias.x;
                o.y = acc[rr][1] + bias.y;
                o.z = acc[rr][2] + bias.z;
                o.w = acc[rr][3] + bias.w;
                *(float4*)&out[(((size_t)b * HW_ + gy) * HW_ + gx) * C_ + tx * 4] = o;
            }
        }
    }
}

// ---------------------------------------------------------------------------
extern "C" void kernel_launch(void* const* d_in, const int* in_sizes, int n_in,
                              void* d_out, int out_size)
{
    (void)in_sizes; (void)n_in; (void)out_size;
    const float* x          = (const float*)d_in[0];
    const float* qkv_w      = (const float*)d_in[1];
    const float* qkv_b      = (const float*)d_in[2];
    const float* proj_w     = (const float*)d_in[3];
    const float* proj_b     = (const float*)d_in[4];
    const float* bias_table = (const float*)d_in[5];
    float* out = (float*)d_out;

    k_qkv <<<BNW, 256>>>(x, qkv_w, qkv_b);
    k_attn<<<dim3(BNW, NH_), 128>>>(bias_table);
    k_proj<<<BNW, 256>>>(proj_w, proj_b, out);
}

// round 6
// speedup vs baseline: 1.0526x; 1.0526x over previous
#include <cuda_runtime.h>

// Swin shifted-window MSA: B=32, H=W=112, C=96, ws=7, ss=3, nh=3, hd=32
// Round 5: convert all GEMM inner loops to packed fp32 FFMA2 (PTX fma.rn.f32x2),
// which runs at 2x the scalar FFMA rate on sm_103a.

#define WS_ 7
#define SS_ 3
#define NH_ 3
#define HD_ 32
#define C_  96
#define N_  49
#define HW_ 112
#define BNW 8192   // 32 * 16 * 16 windows

typedef unsigned long long ull;

// scratch (static device globals; no allocation in kernel_launch)
__device__ float g_qkv[(size_t)BNW * 3 * 3 * N_ * HD_]; // [win][head][which][n][d]
__device__ float g_y[(size_t)BNW * N_ * C_];            // [win][n][c]

__device__ __forceinline__ int rcode(int h) {
    return h < (HW_ - WS_) ? 0 : (h < (HW_ - SS_) ? 1 : 2);
}

// ---- packed f32x2 helpers ------------------------------------------------
__device__ __forceinline__ ull splat2(float v) {
    ull r; asm("mov.b64 %0, {%1, %1};" : "=l"(r) : "f"(v)); return r;
}
__device__ __forceinline__ void ffma2(ull& d, ull a, ull b) {
    asm("fma.rn.f32x2 %0, %1, %2, %0;" : "+l"(d) : "l"(a), "l"(b));
}
__device__ __forceinline__ float2 unpack2(ull v) {
    float2 r; asm("mov.b64 {%0, %1}, %2;" : "=f"(r.x), "=f"(r.y) : "l"(v)); return r;
}

// ---------------------------------------------------------------------------
// Kernel 1: QKV projection. grid = BNW, block = 128.
// Row-pair FFMA2: acc pair = (row n, row n+1) for one output column.
// ---------------------------------------------------------------------------
__global__ __launch_bounds__(128) void k_qkv(
    const float* __restrict__ x,
    const float* __restrict__ qkv_w,
    const float* __restrict__ qkv_b)
{
    __shared__ __align__(16) float xsT[C_][50];  // transposed window [k][n]
    __shared__ __align__(16) float wt[48][C_];   // half of a 96x96 weight tile

    const int bw  = blockIdx.x;
    const int tid = threadIdx.x;
    const int b   = bw >> 8;
    const int w   = bw & 255;
    const int wy  = w >> 4, wx = w & 15;

    // gather rolled window (transposed into smem)
    for (int u = tid; u < N_ * 24; u += 128) {
        int n = u / 24, f4 = u % 24;
        int i = n / 7, j = n % 7;
        int gy = wy * 7 + i + SS_; if (gy >= HW_) gy -= HW_;
        int gx = wx * 7 + j + SS_; if (gx >= HW_) gx -= HW_;
        float4 v = *(const float4*)&x[(((size_t)b * HW_ + gy) * HW_ + gx) * C_ + f4 * 4];
        xsT[f4 * 4 + 0][n] = v.x; xsT[f4 * 4 + 1][n] = v.y;
        xsT[f4 * 4 + 2][n] = v.z; xsT[f4 * 4 + 3][n] = v.w;
    }
    if (tid < C_) xsT[tid][49] = 0.0f;  // pad row for row-pairing

    const int tx = tid % 24;   // column group (4 cols) within 96
    const int ty = tid / 24;   // 0..4 active (10 rows each), ty==5 idles

    for (int which = 0; which < 3; which++) {
        ull acc[5][4] = {};    // 5 row-pairs x 4 cols
        for (int half = 0; half < 2; half++) {
            __syncthreads();
            for (int u = tid; u < 48 * 24; u += 128) {
                int r = u / 24, f = u % 24;
                *(float4*)&wt[r][f * 4] =
                    *(const float4*)&qkv_w[(half * 48 + r) * (3 * C_) + which * C_ + f * 4];
            }
            __syncthreads();
            if (ty < 5) {
                #pragma unroll 4
                for (int kk = 0; kk < 48; kk++) {
                    float4 wv = *(float4*)&wt[kk][tx * 4];
                    ull w0 = splat2(wv.x), w1 = splat2(wv.y);
                    ull w2 = splat2(wv.z), w3 = splat2(wv.w);
                    const float* xr = &xsT[half * 48 + kk][ty * 10];
                    #pragma unroll
                    for (int p = 0; p < 5; p++) {
                        ull xp = *(const ull*)(xr + 2 * p);
                        ffma2(acc[p][0], xp, w0);
                        ffma2(acc[p][1], xp, w1);
                        ffma2(acc[p][2], xp, w2);
                        ffma2(acc[p][3], xp, w3);
                    }
                }
            }
        }
        if (ty < 5) {
            int c = tx * 4;
            int head = c >> 5, d = c & 31;
            float4 bias = *(const float4*)&qkv_b[which * C_ + c];
            float scale = (which == 0) ? 0.17677669529663687f : 1.0f; // hd^-0.5 (q only)
            size_t obase = ((size_t)(bw * 3 + head) * 3 + which) * (size_t)(N_ * HD_);
            #pragma unroll
            for (int p = 0; p < 5; p++) {
                float2 a0 = unpack2(acc[p][0]), a1 = unpack2(acc[p][1]);
                float2 a2 = unpack2(acc[p][2]), a3 = unpack2(acc[p][3]);
                int n = ty * 10 + 2 * p;
                float4 o;
                o.x = (a0.x + bias.x) * scale; o.y = (a1.x + bias.y) * scale;
                o.z = (a2.x + bias.z) * scale; o.w = (a3.x + bias.w) * scale;
                *(float4*)&g_qkv[obase + n * HD_ + d] = o;
                if (n + 1 < N_) {
                    o.x = (a0.y + bias.x) * scale; o.y = (a1.y + bias.y) * scale;
                    o.z = (a2.y + bias.z) * scale; o.w = (a3.y + bias.w) * scale;
                    *(float4*)&g_qkv[obase + (n + 1) * HD_ + d] = o;
                }
            }
        }
    }
}

// ---------------------------------------------------------------------------
// Kernel 2: windowed attention. grid = (BNW, 3), block = 128.
// ---------------------------------------------------------------------------
__global__ __launch_bounds__(128) void k_attn(const float* __restrict__ bias_table)
{
    __shared__ __align__(16) float qs[52][HD_];
    __shared__ __align__(16) float kT[HD_][56];
    __shared__ __align__(16) float vs[52][HD_];
    __shared__ __align__(16) float S[52][56];
    __shared__ int code[52];

    const int bw   = blockIdx.x;
    const int head = blockIdx.y;
    const int tid  = threadIdx.x;
    const size_t base = (size_t)(bw * 3 + head) * 3 * (size_t)(N_ * HD_);

    for (int u = tid; u < N_ * HD_; u += 128) {
        int n = u >> 5, d = u & 31;
        qs[n][d] = g_qkv[base + u];
        kT[d][n] = g_qkv[base + N_ * HD_ + u];
        vs[n][d] = g_qkv[base + 2 * N_ * HD_ + u];
    }
    {
        int w = bw & 255;
        int wy = w >> 4, wx = w & 15;
        for (int n = tid; n < N_; n += 128) {
            int i = n / 7, j = n % 7;
            int gy = wy * 7 + i + SS_; if (gy >= HW_) gy -= HW_;
            int gx = wx * 7 + j + SS_; if (gx >= HW_) gx -= HW_;
            code[n] = rcode(gy) * 3 + rcode(gx);
        }
    }
    __syncthreads();

    // S = q @ k^T  (49x49, K=32): 13 x 7 tiles of 4 rows x 8 cols (m-pair packed)
    if (tid < 91) {
        int n0 = (tid / 7) * 4, m0 = (tid % 7) * 8;
        ull acc[4][4] = {};
        #pragma unroll 8
        for (int kk = 0; kk < HD_; kk++) {
            ulonglong2 ka = *(const ulonglong2*)&kT[kk][m0];
            ulonglong2 kb = *(const ulonglong2*)&kT[kk][m0 + 4];
            #pragma unroll
            for (int r = 0; r < 4; r++) {
                ull qsp = splat2(qs[n0 + r][kk]);
                ffma2(acc[r][0], ka.x, qsp);
                ffma2(acc[r][1], ka.y, qsp);
                ffma2(acc[r][2], kb.x, qsp);
                ffma2(acc[r][3], kb.y, qsp);
            }
        }
        #pragma unroll
        for (int r = 0; r < 4; r++) {
            ull* sr = (ull*)&S[n0 + r][m0];
            sr[0] = acc[r][0]; sr[1] = acc[r][1];
            sr[2] = acc[r][2]; sr[3] = acc[r][3];
        }
    }
    __syncthreads();

    // softmax rows, with relative-position bias + analytic shift mask
    const int wid = tid >> 5, lane = tid & 31;
    for (int r = wid; r < N_; r += 4) {
        int i1 = r / 7, j1 = r % 7, c1 = code[r];
        int m1 = lane, m2 = lane + 32;
        int i2 = m1 / 7, j2 = m1 % 7;
        float b1 = __ldg(&bias_table[((i1 - i2 + 6) * 13 + (j1 - j2 + 6)) * NH_ + head]);
        float v1 = S[r][m1] + b1 + (code[m1] == c1 ? 0.0f : -1e9f);
        float v2 = -1e30f;
        if (m2 < N_) {
            int i3 = m2 / 7, j3 = m2 % 7;
            float b2 = __ldg(&bias_table[((i1 - i3 + 6) * 13 + (j1 - j3 + 6)) * NH_ + head]);
            v2 = S[r][m2] + b2 + (code[m2] == c1 ? 0.0f : -1e9f);
        }
        float mx = fmaxf(v1, v2);
        #pragma unroll
        for (int o = 16; o > 0; o >>= 1) mx = fmaxf(mx, __shfl_xor_sync(0xffffffffu, mx, o));
        float e1 = __expf(v1 - mx);
        float e2 = (m2 < N_) ? __expf(v2 - mx) : 0.0f;
        float sum = e1 + e2;
        #pragma unroll
        for (int o = 16; o > 0; o >>= 1) sum += __shfl_xor_sync(0xffffffffu, sum, o);
        float inv = 1.0f / sum;
        S[r][m1] = e1 * inv;
        if (m2 < N_) S[r][m2] = e2 * inv;
    }
    __syncthreads();

    // O = P @ V  (49x32, K=49): 25 x 4 tiles of 2 rows x 8 d (d-pair packed)
    if (tid < 100) {
        int n0 = (tid >> 2) * 2, d0 = (tid & 3) * 8;
        ull acc[2][4] = {};
        for (int m = 0; m < N_; m++) {
            ulonglong2 va = *(const ulonglong2*)&vs[m][d0];
            ulonglong2 vb = *(const ulonglong2*)&vs[m][d0 + 4];
            ull p0 = splat2(S[n0][m]);
            ull p1 = splat2(S[n0 + 1][m]);
            ffma2(acc[0][0], va.x, p0); ffma2(acc[0][1], va.y, p0);
            ffma2(acc[0][2], vb.x, p0); ffma2(acc[0][3], vb.y, p0);
            ffma2(acc[1][0], va.x, p1); ffma2(acc[1][1], va.y, p1);
            ffma2(acc[1][2], vb.x, p1); ffma2(acc[1][3], vb.y, p1);
        }
        #pragma unroll
        for (int r = 0; r < 2; r++) {
            int n = n0 + r;
            if (n < N_) {
                ull* o = (ull*)&g_y[((size_t)bw * N_ + n) * C_ + head * HD_ + d0];
                o[0] = acc[r][0]; o[1] = acc[r][1];
                o[2] = acc[r][2]; o[3] = acc[r][3];
            }
        }
    }
}

// ---------------------------------------------------------------------------
// Kernel 3: output projection + roll-scatter. grid = BNW, block = 128.
// ---------------------------------------------------------------------------
__global__ __launch_bounds__(128) void k_proj(
    const float* __restrict__ proj_w,
    const float* __restrict__ proj_b,
    float* __restrict__ out)
{
    __shared__ __align__(16) float ysT[C_][50];
    __shared__ __align__(16) float wt[48][C_];

    const int bw  = blockIdx.x;
    const int tid = threadIdx.x;

    for (int u = tid; u < N_ * 24; u += 128) {
        int n = u / 24, f4 = u % 24;
        float4 v = *(const float4*)&g_y[(size_t)bw * (N_ * C_) + n * C_ + f4 * 4];
        ysT[f4 * 4 + 0][n] = v.x; ysT[f4 * 4 + 1][n] = v.y;
        ysT[f4 * 4 + 2][n] = v.z; ysT[f4 * 4 + 3][n] = v.w;
    }
    if (tid < C_) ysT[tid][49] = 0.0f;

    const int tx = tid % 24;
    const int ty = tid / 24;

    ull acc[5][4] = {};
    for (int half = 0; half < 2; half++) {
        __syncthreads();
        for (int u = tid; u < 48 * 24; u += 128) {
            int r = u / 24, f = u % 24;
            *(float4*)&wt[r][f * 4] =
                *(const float4*)&proj_w[(half * 48 + r) * C_ + f * 4];
        }
        __syncthreads();
        if (ty < 5) {
            #pragma unroll 4
            for (int kk = 0; kk < 48; kk++) {
                float4 wv = *(float4*)&wt[kk][tx * 4];
                ull w0 = splat2(wv.x), w1 = splat2(wv.y);
                ull w2 = splat2(wv.z), w3 = splat2(wv.w);
                const float* yr = &ysT[half * 48 + kk][ty * 10];
                #pragma unroll
                for (int p = 0; p < 5; p++) {
                    ull yp = *(const ull*)(yr + 2 * p);
                    ffma2(acc[p][0], yp, w0);
                    ffma2(acc[p][1], yp, w1);
                    ffma2(acc[p][2], yp, w2);
                    ffma2(acc[p][3], yp, w3);
                }
            }
        }
    }

    if (ty < 5) {
        const int b  = bw >> 8;
        const int w  = bw & 255;
        const int wy = w >> 4, wx = w & 15;
        float4 bias = *(const float4*)&proj_b[tx * 4];
        #pragma unroll
        for (int p = 0; p < 5; p++) {
            float2 a0 = unpack2(acc[p][0]), a1 = unpack2(acc[p][1]);
            float2 a2 = unpack2(acc[p][2]), a3 = unpack2(acc[p][3]);
            float r0[2] = {a0.x, a0.y}, r1[2] = {a1.x, a1.y};
            float r2[2] = {a2.x, a2.y}, r3[2] = {a3.x, a3.y};
            #pragma unroll
            for (int h = 0; h < 2; h++) {
                int n = ty * 10 + 2 * p + h;
                if (n < N_) {
                    int i = n / 7, j = n % 7;
                    int gy = wy * 7 + i + SS_; if (gy >= HW_) gy -= HW_;
                    int gx = wx * 7 + j + SS_; if (gx >= HW_) gx -= HW_;
                    float4 o;
                    o.x = r0[h] + bias.x; o.y = r1[h] + bias.y;
                    o.z = r2[h] + bias.z; o.w = r3[h] + bias.w;
                    *(float4*)&out[(((size_t)b * HW_ + gy) * HW_ + gx) * C_ + tx * 4] = o;
                }
            }
        }
    }
}

// ---------------------------------------------------------------------------
extern "C" void kernel_launch(void* const* d_in, const int* in_sizes, int n_in,
                              void* d_out, int out_size)
{
    (void)in_sizes; (void)n_in; (void)out_size;
    const float* x          = (const float*)d_in[0];
    const float* qkv_w      = (const float*)d_in[1];
    const float* qkv_b      = (const float*)d_in[2];
    const float* proj_w     = (const float*)d_in[3];
    const float* proj_b     = (const float*)d_in[4];
    const float* bias_table = (const float*)d_in[5];
    float* out = (float*)d_out;

    k_qkv <<<BNW, 128>>>(x, qkv_w, qkv_b);
    k_attn<<<dim3(BNW, NH_), 128>>>(bias_table);
    k_proj<<<BNW, 128>>>(proj_w, proj_b, out);
}